// round 2
// baseline (speedup 1.0000x reference)
#include <cuda_runtime.h>
#include <cstdint>

#define DD 256          // feature dim
#define HH 512          // hidden dim
#define ROWS 8          // batch rows per block
#define NT 256          // threads per block

typedef unsigned long long u64;

// Packed transposed weights: [K/4][N] float4 (float4 holds 4 consecutive k for col j)
__device__ float4 g_W1p[(DD / 4) * HH];   // K=DD, N=HH
__device__ float4 g_W2p[(HH / 4) * HH];   // K=HH, N=HH
__device__ float4 g_W3p[(HH / 4) * DD];   // K=HH, N=DD

__global__ void prep_kernel(const float* __restrict__ W1,
                            const float* __restrict__ W2,
                            const float* __restrict__ W3) {
    int idx = blockIdx.x * blockDim.x + threadIdx.x;
    int stride = gridDim.x * blockDim.x;
    float* w1p = (float*)g_W1p;
    float* w2p = (float*)g_W2p;
    float* w3p = (float*)g_W3p;
    // W1 [HH, DD] row-major: W1[j][d]
    for (int i = idx; i < HH * DD; i += stride) {
        int j = i / DD, d = i - j * DD;
        w1p[(((d >> 2) * HH) + j) * 4 + (d & 3)] = W1[i];
    }
    // W2 [HH, HH]: W2[j][d]
    for (int i = idx; i < HH * HH; i += stride) {
        int j = i / HH, d = i - j * HH;
        w2p[(((d >> 2) * HH) + j) * 4 + (d & 3)] = W2[i];
    }
    // W3 [DD, HH]: W3[j][d]
    for (int i = idx; i < DD * HH; i += stride) {
        int j = i / HH, d = i - j * HH;
        w3p[(((d >> 2) * DD) + j) * 4 + (d & 3)] = W3[i];
    }
}

__device__ __forceinline__ u64 pk2(float w) {
    u64 r; asm("mov.b64 %0, {%1, %1};" : "=l"(r) : "f"(w)); return r;
}
__device__ __forceinline__ void fma2(u64& a, u64 y, u64 w) {
    asm("fma.rn.f32x2 %0, %1, %2, %0;" : "+l"(a) : "l"(y), "l"(w));
}
__device__ __forceinline__ float2 up2(u64 a) {
    float2 f; asm("mov.b64 {%0, %1}, %2;" : "=f"(f.x), "=f"(f.y) : "l"(a)); return f;
}

union YV { float4 f; u64 u[2]; };

// One layer: out[N][8] = act( in[K][8] (x) W[K][N] + bias[N] )
// Activations transposed [d][8 rows]. Thread t owns cols t, t+NT, ... (C cols).
template<int K, int N, int C, bool RELU>
__device__ __forceinline__ void layer_t(const float* __restrict__ in,
                                        float* __restrict__ out,
                                        const float4* __restrict__ wp,
                                        const float* __restrict__ sbias,
                                        int t) {
    u64 acc[C][4];
    int j[C];
#pragma unroll
    for (int c = 0; c < C; c++) {
        j[c] = t + c * NT;
        u64 b2 = pk2(sbias[j[c]]);
#pragma unroll
        for (int p = 0; p < 4; p++) acc[c][p] = b2;
    }
    // weight prefetch, distance 2 (covers ~234-cyc L2 latency)
    float4 wc[C], wn[C];
#pragma unroll
    for (int c = 0; c < C; c++) {
        wc[c] = wp[0 * N + j[c]];
        wn[c] = wp[1 * N + j[c]];
    }
#pragma unroll 1
    for (int i = 0; i < K / 4; i++) {
        int ip = (i + 2 < K / 4) ? (i + 2) : i;
        float4 wf[C];
#pragma unroll
        for (int c = 0; c < C; c++) wf[c] = wp[ip * N + j[c]];
        // y chunk: 4 k-values x 8 rows, transposed layout -> pairs come out packed
        YV y[4][2];
#pragma unroll
        for (int q = 0; q < 4; q++) {
            y[q][0].f = *(const float4*)(in + (i * 4 + q) * ROWS);
            y[q][1].f = *(const float4*)(in + (i * 4 + q) * ROWS + 4);
        }
#pragma unroll
        for (int c = 0; c < C; c++) {
            float wv0 = wc[c].x, wv1 = wc[c].y, wv2 = wc[c].z, wv3 = wc[c].w;
            u64 w2;
            w2 = pk2(wv0);
            fma2(acc[c][0], y[0][0].u[0], w2); fma2(acc[c][1], y[0][0].u[1], w2);
            fma2(acc[c][2], y[0][1].u[0], w2); fma2(acc[c][3], y[0][1].u[1], w2);
            w2 = pk2(wv1);
            fma2(acc[c][0], y[1][0].u[0], w2); fma2(acc[c][1], y[1][0].u[1], w2);
            fma2(acc[c][2], y[1][1].u[0], w2); fma2(acc[c][3], y[1][1].u[1], w2);
            w2 = pk2(wv2);
            fma2(acc[c][0], y[2][0].u[0], w2); fma2(acc[c][1], y[2][0].u[1], w2);
            fma2(acc[c][2], y[2][1].u[0], w2); fma2(acc[c][3], y[2][1].u[1], w2);
            w2 = pk2(wv3);
            fma2(acc[c][0], y[3][0].u[0], w2); fma2(acc[c][1], y[3][0].u[1], w2);
            fma2(acc[c][2], y[3][1].u[0], w2); fma2(acc[c][3], y[3][1].u[1], w2);
            wc[c] = wn[c]; wn[c] = wf[c];
        }
    }
#pragma unroll
    for (int c = 0; c < C; c++) {
#pragma unroll
        for (int p = 0; p < 4; p++) {
            float2 v = up2(acc[c][p]);
            if (RELU) { v.x = fmaxf(v.x, 0.0f); v.y = fmaxf(v.y, 0.0f); }
            *(float2*)(out + j[c] * ROWS + p * 2) = v;
        }
    }
}

// Full MLP for 8 rows; all arrays transposed [d][8]. Ends synced.
__device__ __forceinline__ void mlp_eval(const float* __restrict__ in,
                                         float* __restrict__ out,
                                         float* __restrict__ h1,
                                         float* __restrict__ h2,
                                         const float* __restrict__ sb1,
                                         const float* __restrict__ sb2,
                                         const float* __restrict__ sb3,
                                         int t) {
    layer_t<DD, HH, 2, true >(in, h1, g_W1p, sb1, t);
    __syncthreads();
    layer_t<HH, HH, 2, true >(h1, h2, g_W2p, sb2, t);
    __syncthreads();
    layer_t<HH, DD, 1, false>(h2, out, g_W3p, sb3, t);
    __syncthreads();
}

__global__ void __launch_bounds__(NT, 1)
ode_kernel(const float* __restrict__ x0,
           const int* __restrict__ Tp,
           const float* __restrict__ b1,
           const float* __restrict__ b2,
           const float* __restrict__ b3,
           float* __restrict__ out,
           int rows_total) {
    extern __shared__ float sm[];
    float* s_y   = sm;                         // DD*8 each, transposed [d][8]
    float* s_tmp = s_y   + ROWS * DD;
    float* s_k1  = s_tmp + ROWS * DD;
    float* s_k2  = s_k1  + ROWS * DD;
    float* s_k3  = s_k2  + ROWS * DD;
    float* s_k4  = s_k3  + ROWS * DD;
    float* s_k5  = s_k4  + ROWS * DD;
    float* s_k6  = s_k5  + ROWS * DD;
    float* s_h1  = s_k6  + ROWS * DD;          // HH*8
    float* s_h2  = s_h1  + ROWS * HH;          // HH*8
    float* s_b1  = s_h2  + ROWS * HH;          // HH
    float* s_b2  = s_b1  + HH;                 // HH
    float* s_b3  = s_b2  + HH;                 // DD

    const int t = threadIdx.x;
    const int row0 = blockIdx.x * ROWS;

    const int T = *Tp;
    const int nint = T - 1;
    const float hs = (float)(10.0 / (double)(nint * 4));

    const float A21 = (float)(1.0 / 5.0);
    const float A31 = (float)(3.0 / 40.0),       A32 = (float)(9.0 / 40.0);
    const float A41 = (float)(44.0 / 45.0),      A42 = (float)(-56.0 / 15.0),
                A43 = (float)(32.0 / 9.0);
    const float A51 = (float)(19372.0 / 6561.0), A52 = (float)(-25360.0 / 2187.0),
                A53 = (float)(64448.0 / 6561.0), A54 = (float)(-212.0 / 729.0);
    const float A61 = (float)(9017.0 / 3168.0),  A62 = (float)(-355.0 / 33.0),
                A63 = (float)(46732.0 / 5247.0), A64 = (float)(49.0 / 176.0),
                A65 = (float)(-5103.0 / 18656.0);
    const float B1 = (float)(35.0 / 384.0),  B3 = (float)(500.0 / 1113.0),
                B4 = (float)(125.0 / 192.0), B5 = (float)(-2187.0 / 6784.0),
                B6 = (float)(11.0 / 84.0);

    for (int i = t; i < HH; i += NT) { s_b1[i] = b1[i]; s_b2[i] = b2[i]; }
    for (int i = t; i < DD; i += NT) s_b3[i] = b3[i];
    for (int i = t; i < ROWS * DD; i += NT) {
        int d = i >> 3, r = i & 7;
        s_y[i] = (row0 + r < rows_total) ? x0[(size_t)(row0 + r) * DD + d] : 0.0f;
    }
    __syncthreads();

    for (int it = 0; it < nint; it++) {
        for (int ss = 0; ss < 4; ss++) {
            mlp_eval(s_y, s_k1, s_h1, s_h2, s_b1, s_b2, s_b3, t);
            for (int i = t; i < ROWS * DD; i += NT)
                s_tmp[i] = fmaf(hs * A21, s_k1[i], s_y[i]);
            __syncthreads();

            mlp_eval(s_tmp, s_k2, s_h1, s_h2, s_b1, s_b2, s_b3, t);
            for (int i = t; i < ROWS * DD; i += NT)
                s_tmp[i] = fmaf(hs, fmaf(A31, s_k1[i], A32 * s_k2[i]), s_y[i]);
            __syncthreads();

            mlp_eval(s_tmp, s_k3, s_h1, s_h2, s_b1, s_b2, s_b3, t);
            for (int i = t; i < ROWS * DD; i += NT) {
                float s = fmaf(A41, s_k1[i], fmaf(A42, s_k2[i], A43 * s_k3[i]));
                s_tmp[i] = fmaf(hs, s, s_y[i]);
            }
            __syncthreads();

            mlp_eval(s_tmp, s_k4, s_h1, s_h2, s_b1, s_b2, s_b3, t);
            for (int i = t; i < ROWS * DD; i += NT) {
                float s = fmaf(A51, s_k1[i],
                          fmaf(A52, s_k2[i],
                          fmaf(A53, s_k3[i], A54 * s_k4[i])));
                s_tmp[i] = fmaf(hs, s, s_y[i]);
            }
            __syncthreads();

            mlp_eval(s_tmp, s_k5, s_h1, s_h2, s_b1, s_b2, s_b3, t);
            for (int i = t; i < ROWS * DD; i += NT) {
                float s = fmaf(A61, s_k1[i],
                          fmaf(A62, s_k2[i],
                          fmaf(A63, s_k3[i],
                          fmaf(A64, s_k4[i], A65 * s_k5[i]))));
                s_tmp[i] = fmaf(hs, s, s_y[i]);
            }
            __syncthreads();

            mlp_eval(s_tmp, s_k6, s_h1, s_h2, s_b1, s_b2, s_b3, t);
            for (int i = t; i < ROWS * DD; i += NT) {
                float s = fmaf(B1, s_k1[i],
                          fmaf(B3, s_k3[i],
                          fmaf(B4, s_k4[i],
                          fmaf(B5, s_k5[i], B6 * s_k6[i]))));
                s_y[i] = fmaf(hs, s, s_y[i]);
            }
            __syncthreads();
        }
        // store y (transposed smem -> row-major gmem): out[b][it][d]
        for (int i = t; i < ROWS * DD; i += NT) {
            int d = i >> 3, r = i & 7;
            int b = row0 + r;
            if (b < rows_total)
                out[((size_t)b * nint + it) * DD + d] = s_y[i];
        }
        // no sync needed: store only reads s_y; next mlp_eval also only reads s_y
    }
}

extern "C" void kernel_launch(void* const* d_in, const int* in_sizes, int n_in,
                              void* d_out, int out_size) {
    const float* x0 = (const float*)d_in[0];
    const int*   Tp = (const int*)d_in[1];
    const float* W1 = (const float*)d_in[2];
    const float* b1 = (const float*)d_in[3];
    const float* W2 = (const float*)d_in[4];
    const float* b2 = (const float*)d_in[5];
    const float* W3 = (const float*)d_in[6];
    const float* b3 = (const float*)d_in[7];
    float* out = (float*)d_out;

    int rows_total = in_sizes[0] / DD;          // B
    int nblocks = (rows_total + ROWS - 1) / ROWS;

    size_t smem = (size_t)(8 * ROWS * DD + 2 * ROWS * HH + 2 * HH + DD) * sizeof(float);
    cudaFuncSetAttribute(ode_kernel, cudaFuncAttributeMaxDynamicSharedMemorySize,
                         (int)smem);

    prep_kernel<<<64, 256>>>(W1, W2, W3);
    ode_kernel<<<nblocks, NT, smem>>>(x0, Tp, b1, b2, b3, out, rows_total);
}